// round 13
// baseline (speedup 1.0000x reference)
#include <cuda_runtime.h>
#include <cuda_bf16.h>

// Causal BoW = running mean along T. Shapes: B=32, T=2048, C=512, fp32.
//
// Single-pass CHAINED scan (StreamScan-style), BARRIER-FREE, SELF-CLEANING:
//  tile = blockIdx.x = (tk, chain): chain = (b, c-quarter) -> 128 chains;
//  tk = chunk of R=32 rows -> 64 chunks/chain; 8192 tiles.
//  128-thread CTA = one thread per column, 32 rows in registers, 8 CTAs/SM
//  (32 warps/SM). No ticket, no barriers, no shared memory: the
//  publish/consume protocol is entirely per-thread, warps flow
//  independently. Tile i spins only on tile i-128; blocks dispatch in
//  increasing blockIdx order -> progress by induction (StreamScan).
//  Per-column inclusive prefixes published as ONE packed 64-bit word
//  (status<<32 | float bits) via atomicExch BEFORE output stores.
//  Successors spin with volatile 64-bit loads then RESET the slot
//  (consume-and-reset). Last tk level never publishes. All device state
//  returns to zero after every launch: graph-safe, no aux kernels.
//  1/(t+1) from a compile-time __constant__ table: warp-uniform index ->
//  uniform-port LDCU instead of 64 MUFU rcp per thread (R12 issue-bound fix).

#define B_DIM 32
#define T_DIM 2048
#define C_DIM 512
#define R_ROWS 32
#define CGROUP 128
#define NCHAINS 128                      // B_DIM * (C_DIM / CGROUP)
#define NTK (T_DIM / R_ROWS)             // 64
#define NTILES (NCHAINS * NTK)           // 8192

// Compile-time 1/(t+1) table, 2048 entries.
#define I1(n) 1.0f/(float)((n)+1)
#define I4(n)   I1(n),   I1((n)+1),   I1((n)+2),    I1((n)+3)
#define I16(n)  I4(n),   I4((n)+4),   I4((n)+8),    I4((n)+12)
#define I64(n)  I16(n),  I16((n)+16), I16((n)+32),  I16((n)+48)
#define I256(n) I64(n),  I64((n)+64), I64((n)+128), I64((n)+192)
#define I1024(n) I256(n),I256((n)+256),I256((n)+512),I256((n)+768)
__constant__ float c_inv[T_DIM] = { I1024(0), I1024(1024) };

__device__ unsigned long long g_incl[(size_t)NTILES * CGROUP];  // 8 MB packed

__global__ void __launch_bounds__(CGROUP, 8)
causal_bow_scan(const float* __restrict__ x, float* __restrict__ out) {
    const unsigned tid = threadIdx.x;
    const unsigned vt  = blockIdx.x;            // tile id = dispatch order

    const unsigned chain = vt & (NCHAINS - 1);
    const unsigned tk    = vt >> 7;             // vt / NCHAINS
    const unsigned b  = chain >> 2;
    const unsigned cq = chain & 3;
    const unsigned c  = cq * CGROUP + tid;
    const int t0 = (int)tk * R_ROWS;

    const size_t base = (size_t)b * (T_DIM * C_DIM)
                      + (size_t)t0 * C_DIM + c;
    const float* __restrict__ xp = x + base;
    float* __restrict__ op = out + base;

    // Batched independent loads: 32 coalesced 128B lines in flight per warp.
    float v[R_ROWS];
    #pragma unroll
    for (int u = 0; u < R_ROWS; ++u)
        v[u] = __ldg(xp + (size_t)u * C_DIM);

    // Local inclusive scan in registers.
    #pragma unroll
    for (int u = 1; u < R_ROWS; ++u)
        v[u] += v[u - 1];

    // Resolve prefix: per-thread spin on predecessor's packed word, then
    // consume-and-reset so the slot is zero for the next launch.
    float prefix = 0.0f;
    if (vt >= NCHAINS) {
        unsigned long long* predp =
            &g_incl[(size_t)(vt - NCHAINS) * CGROUP + tid];
        unsigned long long pk;
        do { pk = *(volatile unsigned long long*)predp; }
        while ((pk >> 32) == 0ull);
        prefix = __uint_as_float((unsigned)(pk & 0xFFFFFFFFu));
        *(volatile unsigned long long*)predp = 0ull;   // consume-reset
    }

    // Publish inclusive prefix — except the last tk level (no successor).
    // Published BEFORE the output stores so successors unblock early.
    if (vt < NTILES - NCHAINS) {
        const unsigned long long pk = (1ull << 32)
            | (unsigned long long)__float_as_uint(prefix + v[R_ROWS - 1]);
        atomicExch(&g_incl[(size_t)vt * CGROUP + tid], pk);
    }

    // Scaled output: (prefix + incl) * (1/(t+1)) from constant table
    // (warp-uniform index -> uniform-port load). Streaming stores.
    #pragma unroll
    for (int u = 0; u < R_ROWS; ++u)
        __stcs(op + (size_t)u * C_DIM, (prefix + v[u]) * c_inv[t0 + u]);
}

extern "C" void kernel_launch(void* const* d_in, const int* in_sizes, int n_in,
                              void* d_out, int out_size) {
    const float* x = (const float*)d_in[0];
    float* out = (float*)d_out;
    (void)in_sizes; (void)n_in; (void)out_size;

    causal_bow_scan<<<NTILES, CGROUP>>>(x, out);
}

// round 14
// speedup vs baseline: 1.1215x; 1.1215x over previous
#include <cuda_runtime.h>
#include <cuda_bf16.h>

// Causal BoW = running mean along T. Shapes: B=32, T=2048, C=512, fp32.
//
// Single-pass CHAINED scan (StreamScan-style), BARRIER-FREE, SELF-CLEANING.
// = R12 (best: 43.6us scan) + R13's constant reciprocal table (issue fix).
//  tile = blockIdx.x = (tk, chain): chain = (b, c-quarter) -> 128 chains;
//  tk = chunk of R=64 rows -> 32 chunks/chain; 4096 tiles.
//  128-thread CTA = one thread per column, 64 rows in registers, 6 CTAs/SM.
//  No ticket, no barriers, no shared memory: publish/consume is entirely
//  per-thread, warps flow independently. Tile i spins only on tile i-128;
//  blocks dispatch in increasing blockIdx order -> progress by induction.
//  Per-column inclusive prefixes published as ONE packed 64-bit word
//  (status<<32 | float bits) via atomicExch BEFORE output stores.
//  Successors spin with volatile 64-bit loads then RESET the slot
//  (consume-and-reset). Last tk level never publishes. All device state
//  returns to zero after every launch: graph-safe, no aux kernels.
//  1/(t+1) from compile-time __constant__ table: warp-uniform index ->
//  uniform-port load, no MUFU in the store tail (R12->R13 measured win).

#define B_DIM 32
#define T_DIM 2048
#define C_DIM 512
#define R_ROWS 64
#define CGROUP 128
#define NCHAINS 128                      // B_DIM * (C_DIM / CGROUP)
#define NTK (T_DIM / R_ROWS)             // 32
#define NTILES (NCHAINS * NTK)           // 4096

// Compile-time 1/(t+1) table, 2048 entries.
#define I1(n) 1.0f/(float)((n)+1)
#define I4(n)   I1(n),   I1((n)+1),   I1((n)+2),    I1((n)+3)
#define I16(n)  I4(n),   I4((n)+4),   I4((n)+8),    I4((n)+12)
#define I64(n)  I16(n),  I16((n)+16), I16((n)+32),  I16((n)+48)
#define I256(n) I64(n),  I64((n)+64), I64((n)+128), I64((n)+192)
#define I1024(n) I256(n),I256((n)+256),I256((n)+512),I256((n)+768)
__constant__ float c_inv[T_DIM] = { I1024(0), I1024(1024) };

__device__ unsigned long long g_incl[(size_t)NTILES * CGROUP];  // 4 MB packed

__global__ void __launch_bounds__(CGROUP, 6)
causal_bow_scan(const float* __restrict__ x, float* __restrict__ out) {
    const unsigned tid = threadIdx.x;
    const unsigned vt  = blockIdx.x;            // tile id = dispatch order

    const unsigned chain = vt & (NCHAINS - 1);
    const unsigned tk    = vt >> 7;             // vt / NCHAINS
    const unsigned b  = chain >> 2;
    const unsigned cq = chain & 3;
    const unsigned c  = cq * CGROUP + tid;
    const int t0 = (int)tk * R_ROWS;

    const size_t base = (size_t)b * (T_DIM * C_DIM)
                      + (size_t)t0 * C_DIM + c;
    const float* __restrict__ xp = x + base;
    float* __restrict__ op = out + base;

    // Batched independent loads: 64 coalesced 128B lines in flight per warp.
    float v[R_ROWS];
    #pragma unroll
    for (int u = 0; u < R_ROWS; ++u)
        v[u] = __ldg(xp + (size_t)u * C_DIM);

    // Local inclusive scan in registers.
    #pragma unroll
    for (int u = 1; u < R_ROWS; ++u)
        v[u] += v[u - 1];

    // Resolve prefix: per-thread spin on predecessor's packed word, then
    // consume-and-reset so the slot is zero for the next launch.
    float prefix = 0.0f;
    if (vt >= NCHAINS) {
        unsigned long long* predp =
            &g_incl[(size_t)(vt - NCHAINS) * CGROUP + tid];
        unsigned long long pk;
        do { pk = *(volatile unsigned long long*)predp; }
        while ((pk >> 32) == 0ull);
        prefix = __uint_as_float((unsigned)(pk & 0xFFFFFFFFu));
        *(volatile unsigned long long*)predp = 0ull;   // consume-reset
    }

    // Publish inclusive prefix — except the last tk level (no successor).
    // Published BEFORE the 64 output stores so successors unblock early.
    if (vt < NTILES - NCHAINS) {
        const unsigned long long pk = (1ull << 32)
            | (unsigned long long)__float_as_uint(prefix + v[R_ROWS - 1]);
        atomicExch(&g_incl[(size_t)vt * CGROUP + tid], pk);
    }

    // Scaled output: (prefix + incl) * (1/(t+1)) from constant table
    // (warp-uniform index -> uniform-port load). Streaming stores.
    #pragma unroll
    for (int u = 0; u < R_ROWS; ++u)
        __stcs(op + (size_t)u * C_DIM, (prefix + v[u]) * c_inv[t0 + u]);
}

extern "C" void kernel_launch(void* const* d_in, const int* in_sizes, int n_in,
                              void* d_out, int out_size) {
    const float* x = (const float*)d_in[0];
    float* out = (float*)d_out;
    (void)in_sizes; (void)n_in; (void)out_size;

    causal_bow_scan<<<NTILES, CGROUP>>>(x, out);
}

// round 15
// speedup vs baseline: 1.1593x; 1.0337x over previous
#include <cuda_runtime.h>
#include <cuda_bf16.h>

// Causal BoW = running mean along T. Shapes: B=32, T=2048, C=512, fp32.
//
// Single-pass CHAINED scan (StreamScan-style), BARRIER-FREE, SELF-CLEANING.
// = R14 (best: 43.8us scan) + EARLY PREDECESSOR PROBE: the first poll of
//   the predecessor's packed word is issued BEFORE the 64-row load batch,
//   so its L2 round-trip overlaps the load/scan phase. For all tiles whose
//   predecessor is already published (the common case under the 4.6-wave
//   dispatch stagger) the prefix costs zero exposed latency.
//  tile = blockIdx.x = (tk, chain): chain = (b, c-quarter) -> 128 chains;
//  tk = chunk of R=64 rows -> 32 chunks/chain; 4096 tiles.
//  128-thread CTA = one thread per column, 64 rows in registers, 6 CTAs/SM.
//  No ticket, no barriers, no shared memory: publish/consume is entirely
//  per-thread, warps flow independently. Tile i spins only on tile i-128;
//  blocks dispatch in increasing blockIdx order -> progress by induction.
//  Per-column inclusive prefixes published as ONE packed 64-bit word
//  (status<<32 | float bits) via atomicExch BEFORE output stores.
//  Successors read with volatile 64-bit loads then RESET the slot
//  (consume-and-reset). Last tk level never publishes. All device state
//  returns to zero after every launch: graph-safe, no aux kernels.
//  1/(t+1) from compile-time __constant__ table (warp-uniform -> LDCU).

#define B_DIM 32
#define T_DIM 2048
#define C_DIM 512
#define R_ROWS 64
#define CGROUP 128
#define NCHAINS 128                      // B_DIM * (C_DIM / CGROUP)
#define NTK (T_DIM / R_ROWS)             // 32
#define NTILES (NCHAINS * NTK)           // 4096

// Compile-time 1/(t+1) table, 2048 entries.
#define I1(n) 1.0f/(float)((n)+1)
#define I4(n)   I1(n),   I1((n)+1),   I1((n)+2),    I1((n)+3)
#define I16(n)  I4(n),   I4((n)+4),   I4((n)+8),    I4((n)+12)
#define I64(n)  I16(n),  I16((n)+16), I16((n)+32),  I16((n)+48)
#define I256(n) I64(n),  I64((n)+64), I64((n)+128), I64((n)+192)
#define I1024(n) I256(n),I256((n)+256),I256((n)+512),I256((n)+768)
__constant__ float c_inv[T_DIM] = { I1024(0), I1024(1024) };

__device__ unsigned long long g_incl[(size_t)NTILES * CGROUP];  // 4 MB packed

__global__ void __launch_bounds__(CGROUP, 6)
causal_bow_scan(const float* __restrict__ x, float* __restrict__ out) {
    const unsigned tid = threadIdx.x;
    const unsigned vt  = blockIdx.x;            // tile id = dispatch order

    const unsigned chain = vt & (NCHAINS - 1);
    const unsigned tk    = vt >> 7;             // vt / NCHAINS
    const unsigned b  = chain >> 2;
    const unsigned cq = chain & 3;
    const unsigned c  = cq * CGROUP + tid;
    const int t0 = (int)tk * R_ROWS;

    const size_t base = (size_t)b * (T_DIM * C_DIM)
                      + (size_t)t0 * C_DIM + c;
    const float* __restrict__ xp = x + base;
    float* __restrict__ op = out + base;

    // EARLY PROBE: issue the first poll of the predecessor slot before the
    // load batch so its L2 latency overlaps the load/scan phase.
    unsigned long long* predp = nullptr;
    unsigned long long pk = 0ull;
    if (vt >= NCHAINS) {
        predp = &g_incl[(size_t)(vt - NCHAINS) * CGROUP + tid];
        pk = *(volatile unsigned long long*)predp;
    }

    // Batched independent loads: 64 coalesced 128B lines in flight per warp.
    float v[R_ROWS];
    #pragma unroll
    for (int u = 0; u < R_ROWS; ++u)
        v[u] = __ldg(xp + (size_t)u * C_DIM);

    // Local inclusive scan in registers.
    #pragma unroll
    for (int u = 1; u < R_ROWS; ++u)
        v[u] += v[u - 1];

    // Resolve prefix: common case = early probe already valid; otherwise
    // spin. Then consume-and-reset so the slot is zero for the next launch.
    float prefix = 0.0f;
    if (vt >= NCHAINS) {
        while ((pk >> 32) == 0ull)
            pk = *(volatile unsigned long long*)predp;
        prefix = __uint_as_float((unsigned)(pk & 0xFFFFFFFFu));
        *(volatile unsigned long long*)predp = 0ull;   // consume-reset
    }

    // Publish inclusive prefix — except the last tk level (no successor).
    // Published BEFORE the 64 output stores so successors unblock early.
    if (vt < NTILES - NCHAINS) {
        const unsigned long long opk = (1ull << 32)
            | (unsigned long long)__float_as_uint(prefix + v[R_ROWS - 1]);
        atomicExch(&g_incl[(size_t)vt * CGROUP + tid], opk);
    }

    // Scaled output: (prefix + incl) * (1/(t+1)) from constant table
    // (warp-uniform index -> uniform-port load). Streaming stores.
    #pragma unroll
    for (int u = 0; u < R_ROWS; ++u)
        __stcs(op + (size_t)u * C_DIM, (prefix + v[u]) * c_inv[t0 + u]);
}

extern "C" void kernel_launch(void* const* d_in, const int* in_sizes, int n_in,
                              void* d_out, int out_size) {
    const float* x = (const float*)d_in[0];
    float* out = (float*)d_out;
    (void)in_sizes; (void)n_in; (void)out_size;

    causal_bow_scan<<<NTILES, CGROUP>>>(x, out);
}